// round 2
// baseline (speedup 1.0000x reference)
#include <cuda_runtime.h>

#define POP      4096
#define SPLITK   74
#define KCHUNK   56                  // 74*56 = 4144 (padded K)
#define POP_PAD  (SPLITK * KCHUNK)   // 4144
#define BK       8
#define BM       128
#define BN       128
#define KSTEPS   (KCHUNK / BK)       // 7

// Scratch (allocation-free rule: __device__ globals; zero-initialized at load,
// pad rows [4096,4144) are never written so they stay zero -> safe K padding)
__device__ __align__(16) float g_M1[POP_PAD * 256];            // w_p * A_p
__device__ __align__(16) float g_M2[POP_PAD * 256];            // B_p
__device__ __align__(16) float g_part[SPLITK * 256 * 256];     // split-K partials

typedef unsigned long long u64;

__device__ __forceinline__ u64 pack2(float x) {
    u64 r; asm("mov.b64 %0, {%1, %1};" : "=l"(r) : "f"(x)); return r;
}
__device__ __forceinline__ void ffma2(u64& d, u64 a, u64 b) {
    asm("fma.rn.f32x2 %0, %1, %2, %0;" : "+l"(d) : "l"(a), "l"(b));
}

// ---------------------------------------------------------------------------
// Kernel 1 (v2): warp per genome; lane 0-15 -> rows of A (=w*kron(b0..b3)),
// lane 16-31 -> rows of B (=kron(b4..b7)). Row computed by incremental kron
// of four 2-vectors: 4+4+16 mults for 16 values. float4 stores, coalesced.
// ---------------------------------------------------------------------------
__global__ void __launch_bounds__(256) build_kernel(
        const float* __restrict__ w,
        const int*   __restrict__ idx,
        const float* __restrict__ bbg) {
    __shared__ float bb[144];
    const int tid = threadIdx.x;
    if (tid < 144) bb[tid] = bbg[tid];
    __syncthreads();

    const int lane = tid & 31;
    const int g    = blockIdx.x * 8 + (tid >> 5);

    int my = 0;
    if (lane < 8) my = idx[g * 8 + lane];
    const int half = lane >> 4;          // 0 = A half, 1 = B half
    const int r    = lane & 15;
    const int c0 = __shfl_sync(0xffffffffu, my, half * 4 + 0);
    const int c1 = __shfl_sync(0xffffffffu, my, half * 4 + 1);
    const int c2 = __shfl_sync(0xffffffffu, my, half * 4 + 2);
    const int c3 = __shfl_sync(0xffffffffu, my, half * 4 + 3);

    const int b3 = (r >> 3) & 1, b2 = (r >> 2) & 1, b1 = (r >> 1) & 1, b0 = r & 1;
    float v0a = bb[c0 * 4 + b3 * 2], v0b = bb[c0 * 4 + b3 * 2 + 1];
    float v1a = bb[c1 * 4 + b2 * 2], v1b = bb[c1 * 4 + b2 * 2 + 1];
    float v2a = bb[c2 * 4 + b1 * 2], v2b = bb[c2 * 4 + b1 * 2 + 1];
    float v3a = bb[c3 * 4 + b0 * 2], v3b = bb[c3 * 4 + b0 * 2 + 1];

    if (half == 0) { const float wp = __ldg(&w[g]); v0a *= wp; v0b *= wp; }

    // p[X*2+Y] = v0[X]*v1[Y], q[X*2+Y] = v2[X]*v3[Y], out[c] = p[c>>2]*q[c&3]
    const float p0 = v0a * v1a, p1 = v0a * v1b, p2 = v0b * v1a, p3 = v0b * v1b;
    const float q0 = v2a * v3a, q1 = v2a * v3b, q2 = v2b * v3a, q3 = v2b * v3b;

    float* base = (half ? g_M2 : g_M1) + g * 256 + r * 16;
    ((float4*)base)[0] = make_float4(p0 * q0, p0 * q1, p0 * q2, p0 * q3);
    ((float4*)base)[1] = make_float4(p1 * q0, p1 * q1, p1 * q2, p1 * q3);
    ((float4*)base)[2] = make_float4(p2 * q0, p2 * q1, p2 * q2, p2 * q3);
    ((float4*)base)[3] = make_float4(p3 * q0, p3 * q1, p3 * q2, p3 * q3);
}

// ---------------------------------------------------------------------------
// Kernel 2: split-K GEMM  G[a,b] = sum_k M1[k,a] * M2[k,b]
// 128x128 tile, 256 threads, 8x8 micro-tile, FFMA2 (f32x2).
// Grid (2,2,74) = 296 CTAs = one full wave at 2 CTAs/SM.
// ---------------------------------------------------------------------------
__global__ void __launch_bounds__(256, 2) gemm_kernel() {
    __shared__ float As[BK][BM];
    __shared__ float Bs[BK][BN];

    const int tid = threadIdx.x;
    const int a0 = blockIdx.x * BM;
    const int b0 = blockIdx.y * BN;
    const int kbase = blockIdx.z * KCHUNK;

    const int lr = tid >> 5;          // 0..7  (k row within step)
    const int lc = (tid & 31) * 4;    // 0..124 (col, float4)

    const float4* pA = (const float4*)&g_M1[(kbase + lr) * 256 + a0 + lc];
    const float4* pB = (const float4*)&g_M2[(kbase + lr) * 256 + b0 + lc];
    float4 fa = *pA;
    float4 fb = *pB;

    const int ty = tid >> 4;          // 0..15 (m group of 8 rows)
    const int tx = tid & 15;          // 0..15 (n group of 8 cols)

    u64 acc[8][4];
    #pragma unroll
    for (int i = 0; i < 8; i++)
        #pragma unroll
        for (int j = 0; j < 4; j++) acc[i][j] = 0ull;

    for (int kt = 0; kt < KSTEPS; kt++) {
        *(float4*)&As[lr][lc] = fa;
        *(float4*)&Bs[lr][lc] = fb;
        __syncthreads();
        if (kt + 1 < KSTEPS) {        // prefetch next tile
            fa = pA[(kt + 1) * 512];  // 512 float4 = BK rows * 256 floats
            fb = pB[(kt + 1) * 512];
        }
        #pragma unroll
        for (int kk = 0; kk < BK; kk++) {
            float4 aLo = *(const float4*)&As[kk][ty * 8];
            float4 aHi = *(const float4*)&As[kk][ty * 8 + 4];
            ulonglong2 bLo = *(const ulonglong2*)&Bs[kk][tx * 8];
            ulonglong2 bHi = *(const ulonglong2*)&Bs[kk][tx * 8 + 4];
            u64 av[8] = {pack2(aLo.x), pack2(aLo.y), pack2(aLo.z), pack2(aLo.w),
                         pack2(aHi.x), pack2(aHi.y), pack2(aHi.z), pack2(aHi.w)};
            #pragma unroll
            for (int i = 0; i < 8; i++) {
                ffma2(acc[i][0], av[i], bLo.x);
                ffma2(acc[i][1], av[i], bLo.y);
                ffma2(acc[i][2], av[i], bHi.x);
                ffma2(acc[i][3], av[i], bHi.y);
            }
        }
        __syncthreads();
    }

    float* part = &g_part[blockIdx.z * 65536];
    #pragma unroll
    for (int i = 0; i < 8; i++) {
        const int a = a0 + ty * 8 + i;
        float* dst = &part[a * 256 + b0 + tx * 8];
        *(ulonglong2*)(dst)     = make_ulonglong2(acc[i][0], acc[i][1]);
        *(ulonglong2*)(dst + 4) = make_ulonglong2(acc[i][2], acc[i][3]);
    }
}

// ---------------------------------------------------------------------------
// Kernel 3: sum split-K partials (float4-vectorized) and scatter with the
// Kronecker permutation: out[(iH*16+iL)*256 + (jH*16+jL)] = G[iH*16+jH, iL*16+jL]
// ---------------------------------------------------------------------------
__global__ void __launch_bounds__(256) reduce_kernel(float* __restrict__ out) {
    const int t4 = blockIdx.x * 256 + threadIdx.x;   // 0..16383, 4 outputs each
    const float4* src = (const float4*)g_part;
    float4 s = make_float4(0.f, 0.f, 0.f, 0.f);
    #pragma unroll
    for (int k = 0; k < SPLITK; k++) {
        float4 v = src[k * 16384 + t4];
        s.x += v.x; s.y += v.y; s.z += v.z; s.w += v.w;
    }
    const int t = t4 * 4;             // a*256 + b (b multiple of 4)
    const int a = t >> 8, b = t & 255;
    const int iH = a >> 4, jH = a & 15;
    const int iL = b >> 4, jL = b & 15;          // jL multiple of 4
    float* dst = out + (iH * 16 + iL) * 256 + jH * 16 + jL;
    *(float4*)dst = s;                           // 4 consecutive jL -> contiguous
}

extern "C" void kernel_launch(void* const* d_in, const int* in_sizes, int n_in,
                              void* d_out, int out_size) {
    const float* w   = (const float*)d_in[0];   // weights   [4096] f32
    const int*   idx = (const int*)  d_in[1];   // indices   [4096,8] i32
    const float* bb  = (const float*)d_in[2];   // blocks    [36,2,2] f32

    build_kernel<<<POP / 8, 256>>>(w, idx, bb);
    gemm_kernel<<<dim3(2, 2, SPLITK), 256>>>();
    reduce_kernel<<<64, 256>>>((float*)d_out);
}

// round 4
// speedup vs baseline: 1.3384x; 1.3384x over previous
#include <cuda_runtime.h>
#include <cuda_fp16.h>
#include <cstdint>

// ---------------------------------------------------------------------------
// out = sum_p w_p * kron8(blocks[idx[p]])  -> 256x256
// kp_p = A_p (codons 0-3) (x) B_p (codons 4-7); G[a,b] = sum_p (w_p A_p[a]) B_p[b]
// out[(iH*16+iL)*256+(jH*16+jL)] = G[iH*16+jH, iL*16+jL]
// Kron of ternary blocks is ternary => A = w*T. Split w = w_hi + w_lo (fp16):
// A_hi, A_lo, B are EXACT fp16. G = A_hi^T B + A_lo^T B via mma.sync f16->f32.
// ---------------------------------------------------------------------------

#define POP      4096
#define SPLITK   37
#define KCHUNK   112                 // 37*112 = 4144 (padded K; pad rows stay 0)
#define POP_PAD  (SPLITK * KCHUNK)
#define LDT      136                 // padded smem tile row (halfs): conflict-free ldmatrix

// Scratch (__device__ globals zero-init; rows >= 4096 never written -> zero pad)
__device__ __align__(16) __half g_Ahi[POP_PAD * 256];
__device__ __align__(16) __half g_Alo[POP_PAD * 256];
__device__ __align__(16) __half g_Bt [POP_PAD * 256];
__device__ float g_part[SPLITK * 256 * 256];

// ---------------- warp-MMA helpers (sm_80+ PTX, valid at compute_103 base) --
__device__ __forceinline__ unsigned smem_u32(const void* p) {
    unsigned a;
    asm("{ .reg .u64 t; cvta.to.shared.u64 t, %1; cvt.u32.u64 %0, t; }" : "=r"(a) : "l"(p));
    return a;
}
__device__ __forceinline__ void ldsm_x4_t(uint32_t* r, unsigned a) {
    asm volatile("ldmatrix.sync.aligned.m8n8.x4.trans.shared.b16 {%0,%1,%2,%3}, [%4];"
                 : "=r"(r[0]), "=r"(r[1]), "=r"(r[2]), "=r"(r[3]) : "r"(a));
}
__device__ __forceinline__ void ldsm_x2_t(uint32_t* r, unsigned a) {
    asm volatile("ldmatrix.sync.aligned.m8n8.x2.trans.shared.b16 {%0,%1}, [%2];"
                 : "=r"(r[0]), "=r"(r[1]) : "r"(a));
}
__device__ __forceinline__ void mma16816(float* d, const uint32_t* a, const uint32_t* b) {
    asm volatile("mma.sync.aligned.m16n8k16.row.col.f32.f16.f16.f32 "
                 "{%0,%1,%2,%3}, {%4,%5,%6,%7}, {%8,%9}, {%0,%1,%2,%3};"
                 : "+f"(d[0]), "+f"(d[1]), "+f"(d[2]), "+f"(d[3])
                 : "r"(a[0]), "r"(a[1]), "r"(a[2]), "r"(a[3]), "r"(b[0]), "r"(b[1]));
}

// ---------------------------------------------------------------------------
// Kernel 1: build A_hi/A_lo/B in k-major layout g_X[k][a] (rows of 256 halfs).
// grid (32, 2): y=0 -> A side (hi+lo), y=1 -> B side. thread: genome kl=t&127,
// x-half xh=t>>7. Value(x,y) = U[x]*V[y]; a = ((x>>2)<<6)|((y>>2)<<4)|((x&3)<<2)|(y&3)
// -> y-quads are 4 consecutive a: pack as 2x half2, one 8B store.
// ---------------------------------------------------------------------------
__global__ void __launch_bounds__(256) build_kernel(
        const float* __restrict__ w,
        const int*   __restrict__ idx,
        const float* __restrict__ bbg) {
    __shared__ float bb[144];
    const int t = threadIdx.x;
    if (t < 144) bb[t] = bbg[t];
    __syncthreads();

    const int z = blockIdx.x;
    const int aside = (blockIdx.y == 0);
    const int kl = t & 127, xh = t >> 7;
    const int g = z * 128 + kl;
    const int cb = aside ? 0 : 4;

    const int i0 = __ldg(&idx[g * 8 + cb + 0]);
    const int i1 = __ldg(&idx[g * 8 + cb + 1]);
    const int i2 = __ldg(&idx[g * 8 + cb + 2]);
    const int i3 = __ldg(&idx[g * 8 + cb + 3]);

    float b0[4], b1[4], b2[4], b3[4];
    #pragma unroll
    for (int j = 0; j < 4; j++) {
        b0[j] = bb[i0 * 4 + j]; b1[j] = bb[i1 * 4 + j];
        b2[j] = bb[i2 * 4 + j]; b3[j] = bb[i3 * 4 + j];
    }

    // U[(p2+q)*4+(r2+s)] = b0[p,r]*b1[q,s]; V likewise from b2,b3. All ternary.
    float U[16], V[16];
    #pragma unroll
    for (int p = 0; p < 2; p++)
      #pragma unroll
      for (int q = 0; q < 2; q++)
        #pragma unroll
        for (int r = 0; r < 2; r++)
          #pragma unroll
          for (int s = 0; s < 2; s++) {
              U[(p*2+q)*4 + (r*2+s)] = b0[p*2+r] * b1[q*2+s];
              V[(p*2+q)*4 + (r*2+s)] = b2[p*2+r] * b3[q*2+s];
          }

    __half2 Vh[8];
    #pragma unroll
    for (int j = 0; j < 8; j++) Vh[j] = __floats2half2_rn(V[2*j], V[2*j+1]);

    if (aside) {
        const float wf  = __ldg(&w[g]);
        const float whf = __half2float(__float2half_rn(wf));
        const float wlf = __half2float(__float2half_rn(wf - whf));
        #pragma unroll
        for (int xi = 0; xi < 8; xi++) {
            const int x = xh * 8 + xi;
            const __half2 ph = __float2half2_rn(whf * U[x]);  // exact: {0, +/-w_hi}
            const __half2 pl = __float2half2_rn(wlf * U[x]);
            const unsigned abase = ((unsigned)(x >> 2) << 6) | ((unsigned)(x & 3) << 2);
            #pragma unroll
            for (int qq = 0; qq < 4; qq++) {
                __half2 h0 = __hmul2(ph, Vh[2*qq]);
                __half2 h1 = __hmul2(ph, Vh[2*qq+1]);
                __half2 l0 = __hmul2(pl, Vh[2*qq]);
                __half2 l1 = __hmul2(pl, Vh[2*qq+1]);
                const unsigned a = abase | ((unsigned)qq << 4);
                uint2 uh; uh.x = *(unsigned*)&h0; uh.y = *(unsigned*)&h1;
                uint2 ul; ul.x = *(unsigned*)&l0; ul.y = *(unsigned*)&l1;
                *(uint2*)&g_Ahi[(size_t)g * 256 + a] = uh;
                *(uint2*)&g_Alo[(size_t)g * 256 + a] = ul;
            }
        }
    } else {
        #pragma unroll
        for (int xi = 0; xi < 8; xi++) {
            const int x = xh * 8 + xi;
            const __half2 uh2 = __float2half2_rn(U[x]);
            const unsigned abase = ((unsigned)(x >> 2) << 6) | ((unsigned)(x & 3) << 2);
            #pragma unroll
            for (int qq = 0; qq < 4; qq++) {
                __half2 h0 = __hmul2(uh2, Vh[2*qq]);
                __half2 h1 = __hmul2(uh2, Vh[2*qq+1]);
                const unsigned a = abase | ((unsigned)qq << 4);
                uint2 u; u.x = *(unsigned*)&h0; u.y = *(unsigned*)&h1;
                *(uint2*)&g_Bt[(size_t)g * 256 + a] = u;
            }
        }
    }
}

// ---------------------------------------------------------------------------
// Kernel 2: HMMA GEMM. grid (2 mb, 2 nb, 37 z) = 148 CTAs (one full wave).
// CTA: 128x128 fp32 accum (regs), K=112. Tiles k-major in smem [112][136],
// fragments via ldmatrix .trans (both operands). D += Ahi^T*B + Alo^T*B.
// ---------------------------------------------------------------------------
__global__ void __launch_bounds__(256, 1) gemm_kernel() {
    extern __shared__ __half smem[];
    __half* As = smem;                     // [KCHUNK][LDT]
    __half* Al = smem + KCHUNK * LDT;
    __half* Bs = smem + 2 * KCHUNK * LDT;

    const int tid = threadIdx.x, lane = tid & 31, wid = tid >> 5;
    const int mb = blockIdx.x, nb = blockIdx.y, z = blockIdx.z;
    const int kbase = z * KCHUNK;

    // Load tiles: 112 rows x 128 halfs (256B) each, uint4 per thread.
    for (int i = tid; i < KCHUNK * 16; i += 256) {
        const int r = i >> 4, c8 = i & 15;
        const size_t go = (size_t)(kbase + r) * 256;
        const uint4 va = ((const uint4*)&g_Ahi[go + mb * 128])[c8];
        const uint4 vl = ((const uint4*)&g_Alo[go + mb * 128])[c8];
        const uint4 vb = ((const uint4*)&g_Bt [go + nb * 128])[c8];
        *(uint4*)&As[r * LDT + c8 * 8] = va;
        *(uint4*)&Al[r * LDT + c8 * 8] = vl;
        *(uint4*)&Bs[r * LDT + c8 * 8] = vb;
    }
    __syncthreads();

    const int wm = wid & 1;                // m-half: 64 rows
    const int wn = wid >> 1;               // n-quarter: 32 cols
    // a-frag (x4.trans) lane address: row k, col m   (storage is [k][m])
    const int arow = (lane & 7) + ((lane >> 4) << 3);
    const int acol = wm * 64 + ((lane >> 3) & 1) * 8;
    // b-frag (x2.trans): lanes 0-15 meaningful
    const int bl = lane & 15;
    const int brow = (bl & 7) + ((bl >> 3) << 3);

    const unsigned aHi = smem_u32(&As[arow * LDT + acol]);
    const unsigned aLo = smem_u32(&Al[arow * LDT + acol]);
    const unsigned bBa = smem_u32(&Bs[brow * LDT + wn * 32]);

    float acc[4][4][4];
    #pragma unroll
    for (int i = 0; i < 4; i++)
        #pragma unroll
        for (int j = 0; j < 4; j++)
            #pragma unroll
            for (int q = 0; q < 4; q++) acc[i][j][q] = 0.f;

    #pragma unroll
    for (int ks = 0; ks < KCHUNK / 16; ks++) {
        const unsigned ko = (unsigned)(ks * 16 * LDT * 2);
        uint32_t bf[4][2];
        #pragma unroll
        for (int nt = 0; nt < 4; nt++) ldsm_x2_t(bf[nt], bBa + ko + nt * 8 * 2);
        uint32_t ah[4][4], al[4][4];
        #pragma unroll
        for (int mt = 0; mt < 4; mt++) {
            ldsm_x4_t(ah[mt], aHi + ko + mt * 16 * 2);
            ldsm_x4_t(al[mt], aLo + ko + mt * 16 * 2);
        }
        #pragma unroll
        for (int mt = 0; mt < 4; mt++)
            #pragma unroll
            for (int nt = 0; nt < 4; nt++) {
                mma16816(acc[mt][nt], ah[mt], bf[nt]);
                mma16816(acc[mt][nt], al[mt], bf[nt]);
            }
    }

    // Epilogue: c-frag rows T/4 (+8), cols 2*(T%4)+{0,1}
    float* part = g_part + z * 65536;
    const int r0 = mb * 128 + wm * 64;
    const int c0 = nb * 128 + wn * 32;
    #pragma unroll
    for (int mt = 0; mt < 4; mt++)
        #pragma unroll
        for (int nt = 0; nt < 4; nt++) {
            const int a = r0 + mt * 16 + (lane >> 2);
            const int b = c0 + nt * 8 + (lane & 3) * 2;
            *(float2*)&part[a * 256 + b]       = make_float2(acc[mt][nt][0], acc[mt][nt][1]);
            *(float2*)&part[(a + 8) * 256 + b] = make_float2(acc[mt][nt][2], acc[mt][nt][3]);
        }
}

// ---------------------------------------------------------------------------
// Kernel 3: sum 37 partials + Kronecker permutation scatter.
// ---------------------------------------------------------------------------
__global__ void __launch_bounds__(256) reduce_kernel(float* __restrict__ out) {
    const int t4 = blockIdx.x * 256 + threadIdx.x;   // 16384 threads, 4 outputs each
    const float4* src = (const float4*)g_part;
    float4 s = make_float4(0.f, 0.f, 0.f, 0.f);
    #pragma unroll
    for (int k = 0; k < SPLITK; k++) {
        float4 v = src[(size_t)k * 16384 + t4];
        s.x += v.x; s.y += v.y; s.z += v.z; s.w += v.w;
    }
    const int tt = t4 * 4;
    const int a = tt >> 8, b = tt & 255;
    const int iH = a >> 4, jH = a & 15;
    const int iL = b >> 4, jL = b & 15;              // jL multiple of 4
    *(float4*)(out + (iH * 16 + iL) * 256 + jH * 16 + jL) = s;
}

extern "C" void kernel_launch(void* const* d_in, const int* in_sizes, int n_in,
                              void* d_out, int out_size) {
    const float* w   = (const float*)d_in[0];
    const int*   idx = (const int*)  d_in[1];
    const float* bb  = (const float*)d_in[2];

    const int smem_bytes = 3 * KCHUNK * LDT * (int)sizeof(__half);  // 91392
    cudaFuncSetAttribute(gemm_kernel, cudaFuncAttributeMaxDynamicSharedMemorySize, smem_bytes);

    build_kernel<<<dim3(32, 2), 256>>>(w, idx, bb);
    gemm_kernel<<<dim3(2, 2, SPLITK), 256, smem_bytes>>>();
    reduce_kernel<<<64, 256>>>((float*)d_out);
}

// round 5
// speedup vs baseline: 1.9625x; 1.4663x over previous
#include <cuda_runtime.h>
#include <cuda_fp16.h>
#include <cstdint>

// ---------------------------------------------------------------------------
// out = sum_p w_p * kron8(blocks[idx[p]])  -> 256x256
// kp_p = A_p (codons 0-3) (x) B_p (codons 4-7); G[a,b] = sum_p (w_p A_p[a]) B_p[b]
// out[(iH*16+iL)*256+(jH*16+jL)] = G[iH*16+jH, iL*16+jL]
// Kron of ternary blocks is ternary => A = w*T. Split w = w_hi + w_lo (fp16):
// A_hi, A_lo, B are EXACT fp16. G = A_hi^T B + A_lo^T B via mma.sync f16->f32.
// ---------------------------------------------------------------------------

#define POP      4096
#define SPLITK   37
#define KCHUNK   112                 // 37*112 = 4144 (padded K; pad rows stay 0)
#define POP_PAD  (SPLITK * KCHUNK)
#define LDT      136                 // padded smem tile row (halfs): conflict-free ldmatrix

// Scratch (__device__ globals zero-init; rows >= 4096 never written -> zero pad)
__device__ __align__(16) __half g_Ahi[POP_PAD * 256];
__device__ __align__(16) __half g_Alo[POP_PAD * 256];
__device__ __align__(16) __half g_Bt [POP_PAD * 256];
__device__ float g_part[SPLITK * 256 * 256];

// ---------------- warp-MMA helpers (sm_80+ PTX, valid at compute_103 base) --
__device__ __forceinline__ unsigned smem_u32(const void* p) {
    unsigned a;
    asm("{ .reg .u64 t; cvta.to.shared.u64 t, %1; cvt.u32.u64 %0, t; }" : "=r"(a) : "l"(p));
    return a;
}
__device__ __forceinline__ void ldsm_x4_t(uint32_t* r, unsigned a) {
    asm volatile("ldmatrix.sync.aligned.m8n8.x4.trans.shared.b16 {%0,%1,%2,%3}, [%4];"
                 : "=r"(r[0]), "=r"(r[1]), "=r"(r[2]), "=r"(r[3]) : "r"(a));
}
__device__ __forceinline__ void ldsm_x2_t(uint32_t* r, unsigned a) {
    asm volatile("ldmatrix.sync.aligned.m8n8.x2.trans.shared.b16 {%0,%1}, [%2];"
                 : "=r"(r[0]), "=r"(r[1]) : "r"(a));
}
__device__ __forceinline__ void mma16816(float* d, const uint32_t* a, const uint32_t* b) {
    asm volatile("mma.sync.aligned.m16n8k16.row.col.f32.f16.f16.f32 "
                 "{%0,%1,%2,%3}, {%4,%5,%6,%7}, {%8,%9}, {%0,%1,%2,%3};"
                 : "+f"(d[0]), "+f"(d[1]), "+f"(d[2]), "+f"(d[3])
                 : "r"(a[0]), "r"(a[1]), "r"(a[2]), "r"(a[3]), "r"(b[0]), "r"(b[1]));
}

// ---------------------------------------------------------------------------
// Kernel 1 (v4): one thread per (genome, x-row). grid (256, 2): y=0 -> A side
// (hi+lo), y=1 -> B side. 131K threads, ~60 inst each.
// Value(x,y) = U[x]*V[y]; a = ((x>>2)<<6)|((y>>2)<<4)|((x&3)<<2)|(y&3)
// -> each y-quad is 4 consecutive a: 2x half2 packed into one 8B store.
// ---------------------------------------------------------------------------
__global__ void __launch_bounds__(256) build_kernel(
        const float* __restrict__ w,
        const int*   __restrict__ idx,
        const float* __restrict__ bbg) {
    __shared__ float bb[144];
    const int t = threadIdx.x;
    if (t < 144) bb[t] = bbg[t];
    __syncthreads();

    const int gi = blockIdx.x * 256 + t;    // 0..65535
    const int g  = gi >> 4;                 // genome
    const int x  = gi & 15;                 // x-row
    const int aside = (blockIdx.y == 0);
    const int cb = aside ? 0 : 4;

    const int i0 = __ldg(&idx[g * 8 + cb + 0]);
    const int i1 = __ldg(&idx[g * 8 + cb + 1]);
    const int i2 = __ldg(&idx[g * 8 + cb + 2]);
    const int i3 = __ldg(&idx[g * 8 + cb + 3]);

    // U[x] = b0[p*2+r] * b1[q*2+s], x = (p2+q)*4 + (r2+s)
    const float u = bb[i0 * 4 + ((x >> 3) & 1) * 2 + ((x >> 1) & 1)]
                  * bb[i1 * 4 + ((x >> 2) & 1) * 2 + (x & 1)];

    // V[16] = kron(b2, b3) (ternary)
    float V[16];
    #pragma unroll
    for (int p = 0; p < 2; p++)
      #pragma unroll
      for (int q = 0; q < 2; q++)
        #pragma unroll
        for (int r = 0; r < 2; r++)
          #pragma unroll
          for (int s = 0; s < 2; s++)
              V[(p*2+q)*4 + (r*2+s)] = bb[i2 * 4 + p*2 + r] * bb[i3 * 4 + q*2 + s];

    __half2 Vh[8];
    #pragma unroll
    for (int j = 0; j < 8; j++) Vh[j] = __floats2half2_rn(V[2*j], V[2*j+1]);

    const unsigned abase = ((unsigned)(x >> 2) << 6) | ((unsigned)(x & 3) << 2);

    if (aside) {
        const float wf  = __ldg(&w[g]);
        const float whf = __half2float(__float2half_rn(wf));
        const float wlf = __half2float(__float2half_rn(wf - whf));
        const __half2 ph = __float2half2_rn(whf * u);   // exact: {0, +/-w_hi}
        const __half2 pl = __float2half2_rn(wlf * u);
        #pragma unroll
        for (int qq = 0; qq < 4; qq++) {
            __half2 h0 = __hmul2(ph, Vh[2*qq]);
            __half2 h1 = __hmul2(ph, Vh[2*qq+1]);
            __half2 l0 = __hmul2(pl, Vh[2*qq]);
            __half2 l1 = __hmul2(pl, Vh[2*qq+1]);
            const unsigned a = abase | ((unsigned)qq << 4);
            uint2 uh; uh.x = *(unsigned*)&h0; uh.y = *(unsigned*)&h1;
            uint2 ul; ul.x = *(unsigned*)&l0; ul.y = *(unsigned*)&l1;
            *(uint2*)&g_Ahi[(size_t)g * 256 + a] = uh;
            *(uint2*)&g_Alo[(size_t)g * 256 + a] = ul;
        }
    } else {
        const __half2 uh2 = __float2half2_rn(u);
        #pragma unroll
        for (int qq = 0; qq < 4; qq++) {
            __half2 h0 = __hmul2(uh2, Vh[2*qq]);
            __half2 h1 = __hmul2(uh2, Vh[2*qq+1]);
            const unsigned a = abase | ((unsigned)qq << 4);
            uint2 uv; uv.x = *(unsigned*)&h0; uv.y = *(unsigned*)&h1;
            *(uint2*)&g_Bt[(size_t)g * 256 + a] = uv;
        }
    }
}

// ---------------------------------------------------------------------------
// Kernel 2: HMMA GEMM. grid (2 mb, 2 nb, 37 z) = 148 CTAs (one full wave).
// CTA: 128x128 fp32 accum (regs), K=112. Tiles k-major in smem [112][136],
// fragments via ldmatrix .trans (both operands). D += Ahi^T*B + Alo^T*B.
// ---------------------------------------------------------------------------
__global__ void __launch_bounds__(256, 1) gemm_kernel() {
    extern __shared__ __half smem[];
    __half* As = smem;                     // [KCHUNK][LDT]
    __half* Al = smem + KCHUNK * LDT;
    __half* Bs = smem + 2 * KCHUNK * LDT;

    const int tid = threadIdx.x, lane = tid & 31, wid = tid >> 5;
    const int mb = blockIdx.x, nb = blockIdx.y, z = blockIdx.z;
    const int kbase = z * KCHUNK;

    // Load tiles: 112 rows x 128 halfs (256B) each, uint4 per thread.
    for (int i = tid; i < KCHUNK * 16; i += 256) {
        const int r = i >> 4, c8 = i & 15;
        const size_t go = (size_t)(kbase + r) * 256;
        const uint4 va = ((const uint4*)&g_Ahi[go + mb * 128])[c8];
        const uint4 vl = ((const uint4*)&g_Alo[go + mb * 128])[c8];
        const uint4 vb = ((const uint4*)&g_Bt [go + nb * 128])[c8];
        *(uint4*)&As[r * LDT + c8 * 8] = va;
        *(uint4*)&Al[r * LDT + c8 * 8] = vl;
        *(uint4*)&Bs[r * LDT + c8 * 8] = vb;
    }
    __syncthreads();

    const int wm = wid & 1;                // m-half: 64 rows
    const int wn = wid >> 1;               // n-quarter: 32 cols
    const int arow = (lane & 7) + ((lane >> 4) << 3);
    const int acol = wm * 64 + ((lane >> 3) & 1) * 8;
    const int bl = lane & 15;
    const int brow = (bl & 7) + ((bl >> 3) << 3);

    const unsigned aHi = smem_u32(&As[arow * LDT + acol]);
    const unsigned aLo = smem_u32(&Al[arow * LDT + acol]);
    const unsigned bBa = smem_u32(&Bs[brow * LDT + wn * 32]);

    float acc[4][4][4];
    #pragma unroll
    for (int i = 0; i < 4; i++)
        #pragma unroll
        for (int j = 0; j < 4; j++)
            #pragma unroll
            for (int q = 0; q < 4; q++) acc[i][j][q] = 0.f;

    #pragma unroll
    for (int ks = 0; ks < KCHUNK / 16; ks++) {
        const unsigned ko = (unsigned)(ks * 16 * LDT * 2);
        uint32_t bf[4][2];
        #pragma unroll
        for (int nt = 0; nt < 4; nt++) ldsm_x2_t(bf[nt], bBa + ko + nt * 8 * 2);
        uint32_t ah[4][4], al[4][4];
        #pragma unroll
        for (int mt = 0; mt < 4; mt++) {
            ldsm_x4_t(ah[mt], aHi + ko + mt * 16 * 2);
            ldsm_x4_t(al[mt], aLo + ko + mt * 16 * 2);
        }
        #pragma unroll
        for (int mt = 0; mt < 4; mt++)
            #pragma unroll
            for (int nt = 0; nt < 4; nt++) {
                mma16816(acc[mt][nt], ah[mt], bf[nt]);
                mma16816(acc[mt][nt], al[mt], bf[nt]);
            }
    }

    float* part = g_part + z * 65536;
    const int r0 = mb * 128 + wm * 64;
    const int c0 = nb * 128 + wn * 32;
    #pragma unroll
    for (int mt = 0; mt < 4; mt++)
        #pragma unroll
        for (int nt = 0; nt < 4; nt++) {
            const int a = r0 + mt * 16 + (lane >> 2);
            const int b = c0 + nt * 8 + (lane & 3) * 2;
            *(float2*)&part[a * 256 + b]       = make_float2(acc[mt][nt][0], acc[mt][nt][1]);
            *(float2*)&part[(a + 8) * 256 + b] = make_float2(acc[mt][nt][2], acc[mt][nt][3]);
        }
}

// ---------------------------------------------------------------------------
// Kernel 3: sum 37 partials + Kronecker permutation scatter.
// ---------------------------------------------------------------------------
__global__ void __launch_bounds__(256) reduce_kernel(float* __restrict__ out) {
    const int t4 = blockIdx.x * 256 + threadIdx.x;   // 16384 threads, 4 outputs each
    const float4* src = (const float4*)g_part;
    float4 s = make_float4(0.f, 0.f, 0.f, 0.f);
    #pragma unroll
    for (int k = 0; k < SPLITK; k++) {
        float4 v = src[(size_t)k * 16384 + t4];
        s.x += v.x; s.y += v.y; s.z += v.z; s.w += v.w;
    }
    const int tt = t4 * 4;
    const int a = tt >> 8, b = tt & 255;
    const int iH = a >> 4, jH = a & 15;
    const int iL = b >> 4, jL = b & 15;              // jL multiple of 4
    *(float4*)(out + (iH * 16 + iL) * 256 + jH * 16 + jL) = s;
}

extern "C" void kernel_launch(void* const* d_in, const int* in_sizes, int n_in,
                              void* d_out, int out_size) {
    const float* w   = (const float*)d_in[0];
    const int*   idx = (const int*)  d_in[1];
    const float* bb  = (const float*)d_in[2];

    const int smem_bytes = 3 * KCHUNK * LDT * (int)sizeof(__half);  // 91392
    cudaFuncSetAttribute(gemm_kernel, cudaFuncAttributeMaxDynamicSharedMemorySize, smem_bytes);

    build_kernel<<<dim3(256, 2), 256>>>(w, idx, bb);
    gemm_kernel<<<dim3(2, 2, SPLITK), 256, smem_bytes>>>();
    reduce_kernel<<<64, 256>>>((float*)d_out);
}

// round 6
// speedup vs baseline: 2.2586x; 1.1509x over previous
#include <cuda_runtime.h>
#include <cuda_fp16.h>
#include <cstdint>

// ---------------------------------------------------------------------------
// out = sum_p w_p * kron8(blocks[idx[p]])  -> 256x256
// kp_p = A_p (codons 0-3) (x) B_p (codons 4-7); G[a,b] = sum_p (w_p A_p[a]) B_p[b]
// out[(iH*16+iL)*256+(jH*16+jL)] = G[iH*16+jH, iL*16+jL]
// Kron of ternary blocks is ternary => A = w*T. Split w = w_hi + w_lo (fp16):
// A_hi, A_lo, B are EXACT fp16. G = A_hi^T B + A_lo^T B via mma.sync f16->f32.
// R6: operand tiles are GENERATED in smem inside the GEMM kernel (no gmem
// round-trip, no separate build launch).
// ---------------------------------------------------------------------------

#define POP      4096
#define SPLITK   37
#define KCHUNK   112                 // 37*112 = 4144 (padded K; pad genomes -> 0)
#define LDT      136                 // padded smem tile row (halfs)

__device__ float g_part[SPLITK * 256 * 256];

// ---------------- warp-MMA helpers (sm_80+ PTX, valid at compute_103 base) --
__device__ __forceinline__ unsigned smem_u32(const void* p) {
    unsigned a;
    asm("{ .reg .u64 t; cvta.to.shared.u64 t, %1; cvt.u32.u64 %0, t; }" : "=r"(a) : "l"(p));
    return a;
}
__device__ __forceinline__ void ldsm_x4_t(uint32_t* r, unsigned a) {
    asm volatile("ldmatrix.sync.aligned.m8n8.x4.trans.shared.b16 {%0,%1,%2,%3}, [%4];"
                 : "=r"(r[0]), "=r"(r[1]), "=r"(r[2]), "=r"(r[3]) : "r"(a));
}
__device__ __forceinline__ void ldsm_x2_t(uint32_t* r, unsigned a) {
    asm volatile("ldmatrix.sync.aligned.m8n8.x2.trans.shared.b16 {%0,%1}, [%2];"
                 : "=r"(r[0]), "=r"(r[1]) : "r"(a));
}
__device__ __forceinline__ void mma16816(float* d, const uint32_t* a, const uint32_t* b) {
    asm volatile("mma.sync.aligned.m16n8k16.row.col.f32.f16.f16.f32 "
                 "{%0,%1,%2,%3}, {%4,%5,%6,%7}, {%8,%9}, {%0,%1,%2,%3};"
                 : "+f"(d[0]), "+f"(d[1]), "+f"(d[2]), "+f"(d[3])
                 : "r"(a[0]), "r"(a[1]), "r"(a[2]), "r"(a[3]), "r"(b[0]), "r"(b[1]));
}

// ---------------------------------------------------------------------------
// Fused kernel: grid (2 mb, 2 nb, 37 z) = 148 CTAs (one full wave), 256 thr.
// Phase 1: generate As/Al (A hi/lo, k-major [112][LDT]) and Bs in smem.
// Phase 2: 128x128 fp32 accum via mma.sync, D += Ahi^T*B + Alo^T*B.
// ---------------------------------------------------------------------------
__global__ void __launch_bounds__(256, 1) fused_kernel(
        const float* __restrict__ w,
        const int*   __restrict__ idxg,
        const float* __restrict__ bbg) {
    extern __shared__ __half smem[];
    __half* As = smem;                       // [KCHUNK][LDT]
    __half* Al = smem + KCHUNK * LDT;
    __half* Bs = smem + 2 * KCHUNK * LDT;
    __shared__ float bb[144];
    __shared__ int   sidx[KCHUNK * 8];
    __shared__ float sw[KCHUNK];

    const int tid = threadIdx.x, lane = tid & 31, wid = tid >> 5;
    const int mb = blockIdx.x, nb = blockIdx.y, z = blockIdx.z;
    const int gbase = z * KCHUNK;

    // ---- Stage constants: building blocks, indices, weights (coalesced) ----
    if (tid < 144) bb[tid] = bbg[tid];
    #pragma unroll
    for (int i = tid; i < KCHUNK * 8; i += 256) {
        const int g = gbase + (i >> 3);
        sidx[i] = (g < POP) ? __ldg(&idxg[g * 8 + (i & 7)]) : 0;
    }
    if (tid < KCHUNK) {
        const int g = gbase + tid;
        sw[tid] = (g < POP) ? __ldg(&w[g]) : 0.f;   // w=0 -> zero A rows (pad)
    }
    __syncthreads();

    // ---- Phase 1a: A side (hi/lo). (g,x) tasks, x = mb*8 + xi ----
    for (int i = tid; i < KCHUNK * 8; i += 256) {
        const int gl = i >> 3, xi = i & 7;
        const int* ip = &sidx[gl * 8];
        // u = U[x] with x = mb*8+xi: bit3=mb, bit2=(xi>>2), bit1=(xi>>1), bit0=xi
        const float u = bb[ip[0] * 4 + (mb & 1) * 2 + ((xi >> 1) & 1)]
                      * bb[ip[1] * 4 + ((xi >> 2) & 1) * 2 + (xi & 1)];
        float V[16];
        #pragma unroll
        for (int p = 0; p < 2; p++)
          #pragma unroll
          for (int q = 0; q < 2; q++)
            #pragma unroll
            for (int r = 0; r < 2; r++)
              #pragma unroll
              for (int s = 0; s < 2; s++)
                  V[(p*2+q)*4 + (r*2+s)] = bb[ip[2]*4 + p*2 + r] * bb[ip[3]*4 + q*2 + s];

        const float wf  = sw[gl];
        const float whf = __half2float(__float2half_rn(wf));
        const float wlf = __half2float(__float2half_rn(wf - whf));
        const __half2 ph = __float2half2_rn(whf * u);   // exact: {0, +/-w_hi}
        const __half2 pl = __float2half2_rn(wlf * u);

        const int colbase = (((xi >> 2) & 1) << 6) | ((xi & 3) << 2);
        #pragma unroll
        for (int qq = 0; qq < 4; qq++) {
            __half2 v0 = __floats2half2_rn(V[4*qq],   V[4*qq+1]);
            __half2 v1 = __floats2half2_rn(V[4*qq+2], V[4*qq+3]);
            __half2 h0 = __hmul2(ph, v0), h1 = __hmul2(ph, v1);
            __half2 l0 = __hmul2(pl, v0), l1 = __hmul2(pl, v1);
            const int col = colbase | (qq << 4);
            uint2 uh; uh.x = *(unsigned*)&h0; uh.y = *(unsigned*)&h1;
            uint2 ul; ul.x = *(unsigned*)&l0; ul.y = *(unsigned*)&l1;
            *(uint2*)&As[gl * LDT + col] = uh;
            *(uint2*)&Al[gl * LDT + col] = ul;
        }
    }

    // ---- Phase 1b: B side. (g,x) tasks, x = nb*8 + xi ----
    for (int i = tid; i < KCHUNK * 8; i += 256) {
        const int gl = i >> 3, xi = i & 7;
        const int* ip = &sidx[gl * 8];
        float u = bb[ip[4] * 4 + (nb & 1) * 2 + ((xi >> 1) & 1)]
                * bb[ip[5] * 4 + ((xi >> 2) & 1) * 2 + (xi & 1)];
        if (gbase + gl >= POP) u = 0.f;                // zero pad rows
        float V[16];
        #pragma unroll
        for (int p = 0; p < 2; p++)
          #pragma unroll
          for (int q = 0; q < 2; q++)
            #pragma unroll
            for (int r = 0; r < 2; r++)
              #pragma unroll
              for (int s = 0; s < 2; s++)
                  V[(p*2+q)*4 + (r*2+s)] = bb[ip[6]*4 + p*2 + r] * bb[ip[7]*4 + q*2 + s];

        const __half2 uh2 = __float2half2_rn(u);
        const int colbase = (((xi >> 2) & 1) << 6) | ((xi & 3) << 2);
        #pragma unroll
        for (int qq = 0; qq < 4; qq++) {
            __half2 v0 = __floats2half2_rn(V[4*qq],   V[4*qq+1]);
            __half2 v1 = __floats2half2_rn(V[4*qq+2], V[4*qq+3]);
            __half2 h0 = __hmul2(uh2, v0), h1 = __hmul2(uh2, v1);
            const int col = colbase | (qq << 4);
            uint2 uv; uv.x = *(unsigned*)&h0; uv.y = *(unsigned*)&h1;
            *(uint2*)&Bs[gl * LDT + col] = uv;
        }
    }
    __syncthreads();

    // ---- Phase 2: HMMA mainloop (identical to validated R5 scheme) ----
    const int wm = wid & 1;                // m-half: 64 rows
    const int wn = wid >> 1;               // n-quarter: 32 cols
    const int arow = (lane & 7) + ((lane >> 4) << 3);
    const int acol = wm * 64 + ((lane >> 3) & 1) * 8;
    const int bl = lane & 15;
    const int brow = (bl & 7) + ((bl >> 3) << 3);

    const unsigned aHi = smem_u32(&As[arow * LDT + acol]);
    const unsigned aLo = smem_u32(&Al[arow * LDT + acol]);
    const unsigned bBa = smem_u32(&Bs[brow * LDT + wn * 32]);

    float acc[4][4][4];
    #pragma unroll
    for (int i = 0; i < 4; i++)
        #pragma unroll
        for (int j = 0; j < 4; j++)
            #pragma unroll
            for (int q = 0; q < 4; q++) acc[i][j][q] = 0.f;

    #pragma unroll
    for (int ks = 0; ks < KCHUNK / 16; ks++) {
        const unsigned ko = (unsigned)(ks * 16 * LDT * 2);
        uint32_t bf[4][2];
        #pragma unroll
        for (int nt = 0; nt < 4; nt++) ldsm_x2_t(bf[nt], bBa + ko + nt * 8 * 2);
        uint32_t ah[4][4], al[4][4];
        #pragma unroll
        for (int mt = 0; mt < 4; mt++) {
            ldsm_x4_t(ah[mt], aHi + ko + mt * 16 * 2);
            ldsm_x4_t(al[mt], aLo + ko + mt * 16 * 2);
        }
        #pragma unroll
        for (int mt = 0; mt < 4; mt++)
            #pragma unroll
            for (int nt = 0; nt < 4; nt++) {
                mma16816(acc[mt][nt], ah[mt], bf[nt]);
                mma16816(acc[mt][nt], al[mt], bf[nt]);
            }
    }

    // ---- Epilogue: write split-K partial ----
    float* part = g_part + z * 65536;
    const int r0 = mb * 128 + wm * 64;
    const int c0 = nb * 128 + wn * 32;
    #pragma unroll
    for (int mt = 0; mt < 4; mt++)
        #pragma unroll
        for (int nt = 0; nt < 4; nt++) {
            const int a = r0 + mt * 16 + (lane >> 2);
            const int b = c0 + nt * 8 + (lane & 3) * 2;
            *(float2*)&part[a * 256 + b]       = make_float2(acc[mt][nt][0], acc[mt][nt][1]);
            *(float2*)&part[(a + 8) * 256 + b] = make_float2(acc[mt][nt][2], acc[mt][nt][3]);
        }
}

// ---------------------------------------------------------------------------
// Reduce: sum 37 partials + Kronecker permutation scatter.
// ---------------------------------------------------------------------------
__global__ void __launch_bounds__(256) reduce_kernel(float* __restrict__ out) {
    const int t4 = blockIdx.x * 256 + threadIdx.x;   // 16384 threads, 4 outputs each
    const float4* src = (const float4*)g_part;
    float4 s = make_float4(0.f, 0.f, 0.f, 0.f);
    #pragma unroll
    for (int k = 0; k < SPLITK; k++) {
        float4 v = src[(size_t)k * 16384 + t4];
        s.x += v.x; s.y += v.y; s.z += v.z; s.w += v.w;
    }
    const int tt = t4 * 4;
    const int a = tt >> 8, b = tt & 255;
    const int iH = a >> 4, jH = a & 15;
    const int iL = b >> 4, jL = b & 15;              // jL multiple of 4
    *(float4*)(out + (iH * 16 + iL) * 256 + jH * 16 + jL) = s;
}

extern "C" void kernel_launch(void* const* d_in, const int* in_sizes, int n_in,
                              void* d_out, int out_size) {
    const float* w   = (const float*)d_in[0];
    const int*   idx = (const int*)  d_in[1];
    const float* bb  = (const float*)d_in[2];

    const int smem_bytes = 3 * KCHUNK * LDT * (int)sizeof(__half);  // 91392
    cudaFuncSetAttribute(fused_kernel, cudaFuncAttributeMaxDynamicSharedMemorySize, smem_bytes);

    fused_kernel<<<dim3(2, 2, SPLITK), 256, smem_bytes>>>(w, idx, bb);
    reduce_kernel<<<64, 256>>>((float*)d_out);
}

// round 7
// speedup vs baseline: 2.2635x; 1.0022x over previous
#include <cuda_runtime.h>
#include <cuda_fp16.h>
#include <cstdint>

// ---------------------------------------------------------------------------
// out = sum_p w_p * kron8(blocks[idx[p]])  -> 256x256
// kp_p = A_p (codons 0-3) (x) B_p (codons 4-7); G[a,b] = sum_p (w_p A_p[a]) B_p[b]
// out[(iH*16+iL)*256+(jH*16+jL)] = G[iH*16+jH, iL*16+jL]
// Kron of ternary blocks is ternary => A = w*T. Split w = w_hi + w_lo (fp16):
// A_hi, A_lo, B are EXACT fp16. G = A_hi^T B + A_lo^T B via mma.sync f16->f32.
// R6: operand tiles generated in smem inside the GEMM (no gmem round-trip).
// R7: split-K reduce parallelized 4x across k (65K threads, smem combine).
// ---------------------------------------------------------------------------

#define POP      4096
#define SPLITK   37
#define KCHUNK   112                 // 37*112 = 4144 (padded K; pad genomes -> 0)
#define LDT      136                 // padded smem tile row (halfs)

__device__ float g_part[SPLITK * 256 * 256];

// ---------------- warp-MMA helpers (sm_80+ PTX, valid at compute_103 base) --
__device__ __forceinline__ unsigned smem_u32(const void* p) {
    unsigned a;
    asm("{ .reg .u64 t; cvta.to.shared.u64 t, %1; cvt.u32.u64 %0, t; }" : "=r"(a) : "l"(p));
    return a;
}
__device__ __forceinline__ void ldsm_x4_t(uint32_t* r, unsigned a) {
    asm volatile("ldmatrix.sync.aligned.m8n8.x4.trans.shared.b16 {%0,%1,%2,%3}, [%4];"
                 : "=r"(r[0]), "=r"(r[1]), "=r"(r[2]), "=r"(r[3]) : "r"(a));
}
__device__ __forceinline__ void ldsm_x2_t(uint32_t* r, unsigned a) {
    asm volatile("ldmatrix.sync.aligned.m8n8.x2.trans.shared.b16 {%0,%1}, [%2];"
                 : "=r"(r[0]), "=r"(r[1]) : "r"(a));
}
__device__ __forceinline__ void mma16816(float* d, const uint32_t* a, const uint32_t* b) {
    asm volatile("mma.sync.aligned.m16n8k16.row.col.f32.f16.f16.f32 "
                 "{%0,%1,%2,%3}, {%4,%5,%6,%7}, {%8,%9}, {%0,%1,%2,%3};"
                 : "+f"(d[0]), "+f"(d[1]), "+f"(d[2]), "+f"(d[3])
                 : "r"(a[0]), "r"(a[1]), "r"(a[2]), "r"(a[3]), "r"(b[0]), "r"(b[1]));
}

// ---------------------------------------------------------------------------
// Fused kernel: grid (2 mb, 2 nb, 37 z) = 148 CTAs (one full wave), 256 thr.
// Phase 1: generate As/Al (A hi/lo, k-major [112][LDT]) and Bs in smem.
// Phase 2: 128x128 fp32 accum via mma.sync, D += Ahi^T*B + Alo^T*B.
// ---------------------------------------------------------------------------
__global__ void __launch_bounds__(256, 1) fused_kernel(
        const float* __restrict__ w,
        const int*   __restrict__ idxg,
        const float* __restrict__ bbg) {
    extern __shared__ __half smem[];
    __half* As = smem;                       // [KCHUNK][LDT]
    __half* Al = smem + KCHUNK * LDT;
    __half* Bs = smem + 2 * KCHUNK * LDT;
    __shared__ float bb[144];
    __shared__ int   sidx[KCHUNK * 8];
    __shared__ float sw[KCHUNK];

    const int tid = threadIdx.x, lane = tid & 31, wid = tid >> 5;
    const int mb = blockIdx.x, nb = blockIdx.y, z = blockIdx.z;
    const int gbase = z * KCHUNK;

    // ---- Stage constants: building blocks, indices, weights (coalesced) ----
    if (tid < 144) bb[tid] = bbg[tid];
    #pragma unroll
    for (int i = tid; i < KCHUNK * 8; i += 256) {
        const int g = gbase + (i >> 3);
        sidx[i] = (g < POP) ? __ldg(&idxg[g * 8 + (i & 7)]) : 0;
    }
    if (tid < KCHUNK) {
        const int g = gbase + tid;
        sw[tid] = (g < POP) ? __ldg(&w[g]) : 0.f;   // w=0 -> zero A rows (pad)
    }
    __syncthreads();

    // ---- Phase 1a: A side (hi/lo). (g,x) tasks, x = mb*8 + xi ----
    for (int i = tid; i < KCHUNK * 8; i += 256) {
        const int gl = i >> 3, xi = i & 7;
        const int* ip = &sidx[gl * 8];
        const float u = bb[ip[0] * 4 + (mb & 1) * 2 + ((xi >> 1) & 1)]
                      * bb[ip[1] * 4 + ((xi >> 2) & 1) * 2 + (xi & 1)];
        float V[16];
        #pragma unroll
        for (int p = 0; p < 2; p++)
          #pragma unroll
          for (int q = 0; q < 2; q++)
            #pragma unroll
            for (int r = 0; r < 2; r++)
              #pragma unroll
              for (int s = 0; s < 2; s++)
                  V[(p*2+q)*4 + (r*2+s)] = bb[ip[2]*4 + p*2 + r] * bb[ip[3]*4 + q*2 + s];

        const float wf  = sw[gl];
        const float whf = __half2float(__float2half_rn(wf));
        const float wlf = __half2float(__float2half_rn(wf - whf));
        const __half2 ph = __float2half2_rn(whf * u);   // exact: {0, +/-w_hi}
        const __half2 pl = __float2half2_rn(wlf * u);

        const int colbase = (((xi >> 2) & 1) << 6) | ((xi & 3) << 2);
        #pragma unroll
        for (int qq = 0; qq < 4; qq++) {
            __half2 v0 = __floats2half2_rn(V[4*qq],   V[4*qq+1]);
            __half2 v1 = __floats2half2_rn(V[4*qq+2], V[4*qq+3]);
            __half2 h0 = __hmul2(ph, v0), h1 = __hmul2(ph, v1);
            __half2 l0 = __hmul2(pl, v0), l1 = __hmul2(pl, v1);
            const int col = colbase | (qq << 4);
            uint2 uh; uh.x = *(unsigned*)&h0; uh.y = *(unsigned*)&h1;
            uint2 ul; ul.x = *(unsigned*)&l0; ul.y = *(unsigned*)&l1;
            *(uint2*)&As[gl * LDT + col] = uh;
            *(uint2*)&Al[gl * LDT + col] = ul;
        }
    }

    // ---- Phase 1b: B side. (g,x) tasks, x = nb*8 + xi ----
    for (int i = tid; i < KCHUNK * 8; i += 256) {
        const int gl = i >> 3, xi = i & 7;
        const int* ip = &sidx[gl * 8];
        float u = bb[ip[4] * 4 + (nb & 1) * 2 + ((xi >> 1) & 1)]
                * bb[ip[5] * 4 + ((xi >> 2) & 1) * 2 + (xi & 1)];
        if (gbase + gl >= POP) u = 0.f;                // zero pad rows
        float V[16];
        #pragma unroll
        for (int p = 0; p < 2; p++)
          #pragma unroll
          for (int q = 0; q < 2; q++)
            #pragma unroll
            for (int r = 0; r < 2; r++)
              #pragma unroll
              for (int s = 0; s < 2; s++)
                  V[(p*2+q)*4 + (r*2+s)] = bb[ip[6]*4 + p*2 + r] * bb[ip[7]*4 + q*2 + s];

        const __half2 uh2 = __float2half2_rn(u);
        const int colbase = (((xi >> 2) & 1) << 6) | ((xi & 3) << 2);
        #pragma unroll
        for (int qq = 0; qq < 4; qq++) {
            __half2 v0 = __floats2half2_rn(V[4*qq],   V[4*qq+1]);
            __half2 v1 = __floats2half2_rn(V[4*qq+2], V[4*qq+3]);
            __half2 h0 = __hmul2(uh2, v0), h1 = __hmul2(uh2, v1);
            const int col = colbase | (qq << 4);
            uint2 uv; uv.x = *(unsigned*)&h0; uv.y = *(unsigned*)&h1;
            *(uint2*)&Bs[gl * LDT + col] = uv;
        }
    }
    __syncthreads();

    // ---- Phase 2: HMMA mainloop ----
    const int wm = wid & 1;                // m-half: 64 rows
    const int wn = wid >> 1;               // n-quarter: 32 cols
    const int arow = (lane & 7) + ((lane >> 4) << 3);
    const int acol = wm * 64 + ((lane >> 3) & 1) * 8;
    const int bl = lane & 15;
    const int brow = (bl & 7) + ((bl >> 3) << 3);

    const unsigned aHi = smem_u32(&As[arow * LDT + acol]);
    const unsigned aLo = smem_u32(&Al[arow * LDT + acol]);
    const unsigned bBa = smem_u32(&Bs[brow * LDT + wn * 32]);

    float acc[4][4][4];
    #pragma unroll
    for (int i = 0; i < 4; i++)
        #pragma unroll
        for (int j = 0; j < 4; j++)
            #pragma unroll
            for (int q = 0; q < 4; q++) acc[i][j][q] = 0.f;

    #pragma unroll
    for (int ks = 0; ks < KCHUNK / 16; ks++) {
        const unsigned ko = (unsigned)(ks * 16 * LDT * 2);
        uint32_t bf[4][2];
        #pragma unroll
        for (int nt = 0; nt < 4; nt++) ldsm_x2_t(bf[nt], bBa + ko + nt * 8 * 2);
        uint32_t ah[4][4], al[4][4];
        #pragma unroll
        for (int mt = 0; mt < 4; mt++) {
            ldsm_x4_t(ah[mt], aHi + ko + mt * 16 * 2);
            ldsm_x4_t(al[mt], aLo + ko + mt * 16 * 2);
        }
        #pragma unroll
        for (int mt = 0; mt < 4; mt++)
            #pragma unroll
            for (int nt = 0; nt < 4; nt++) {
                mma16816(acc[mt][nt], ah[mt], bf[nt]);
                mma16816(acc[mt][nt], al[mt], bf[nt]);
            }
    }

    // ---- Epilogue: write split-K partial ----
    float* part = g_part + z * 65536;
    const int r0 = mb * 128 + wm * 64;
    const int c0 = nb * 128 + wn * 32;
    #pragma unroll
    for (int mt = 0; mt < 4; mt++)
        #pragma unroll
        for (int nt = 0; nt < 4; nt++) {
            const int a = r0 + mt * 16 + (lane >> 2);
            const int b = c0 + nt * 8 + (lane & 3) * 2;
            *(float2*)&part[a * 256 + b]       = make_float2(acc[mt][nt][0], acc[mt][nt][1]);
            *(float2*)&part[(a + 8) * 256 + b] = make_float2(acc[mt][nt][2], acc[mt][nt][3]);
        }
}

// ---------------------------------------------------------------------------
// Reduce v2: 4 k-groups per output. grid 256 x 256 thr (65K threads).
// Thread (blk, t): t4 = blk*64 + (t&63), ks = t>>6 in 0..3 sums slices
// [k0, k0+cnt) with cnt = 10,9,9,9. Combine via smem, permute, store.
// ---------------------------------------------------------------------------
__global__ void __launch_bounds__(256) reduce_kernel(float* __restrict__ out) {
    __shared__ float4 red[3][64];
    const int t = threadIdx.x;
    const int t4 = blockIdx.x * 64 + (t & 63);
    const int ks = t >> 6;                           // 0..3
    const int k0  = ks * 9 + (ks > 0 ? 1 : 0);       // 0,10,19,28
    const int cnt = (ks == 0) ? 10 : 9;

    const float4* src = (const float4*)g_part + t4;
    float4 s = make_float4(0.f, 0.f, 0.f, 0.f);
    #pragma unroll 10
    for (int k = 0; k < cnt; k++) {
        float4 v = src[(size_t)(k0 + k) * 16384];
        s.x += v.x; s.y += v.y; s.z += v.z; s.w += v.w;
    }
    if (ks > 0) red[ks - 1][t & 63] = s;
    __syncthreads();
    if (ks == 0) {
        #pragma unroll
        for (int j = 0; j < 3; j++) {
            float4 v = red[j][t];
            s.x += v.x; s.y += v.y; s.z += v.z; s.w += v.w;
        }
        const int tt = t4 * 4;
        const int a = tt >> 8, b = tt & 255;
        const int iH = a >> 4, jH = a & 15;
        const int iL = b >> 4, jL = b & 15;          // jL multiple of 4
        *(float4*)(out + (iH * 16 + iL) * 256 + jH * 16 + jL) = s;
    }
}

extern "C" void kernel_launch(void* const* d_in, const int* in_sizes, int n_in,
                              void* d_out, int out_size) {
    const float* w   = (const float*)d_in[0];
    const int*   idx = (const int*)  d_in[1];
    const float* bb  = (const float*)d_in[2];

    const int smem_bytes = 3 * KCHUNK * LDT * (int)sizeof(__half);  // 91392
    cudaFuncSetAttribute(fused_kernel, cudaFuncAttributeMaxDynamicSharedMemorySize, smem_bytes);

    fused_kernel<<<dim3(2, 2, SPLITK), 256, smem_bytes>>>(w, idx, bb);
    reduce_kernel<<<256, 256>>>((float*)d_out);
}

// round 8
// speedup vs baseline: 2.6266x; 1.1604x over previous
#include <cuda_runtime.h>
#include <cuda_fp16.h>
#include <cstdint>

// ---------------------------------------------------------------------------
// out = sum_p w_p * kron8(blocks[idx[p]])  -> 256x256
// kp_p = A_p (codons 0-3) (x) B_p (codons 4-7); G[a,b] = sum_p (w_p A_p[a]) B_p[b]
// out[(iH*16+iL)*256+(jH*16+jL)] = G[iH*16+jH, iL*16+jL]
// Kron of ternary blocks is ternary => A = w*T. Split w = w_hi + w_lo (fp16):
// A_hi, A_lo, B are EXACT fp16. G = A_hi^T B + A_lo^T B via mma.sync f16->f32.
// R6: operand tiles generated in smem inside the GEMM (no gmem round-trip).
// R8: reduce uses constant-bound fully-unrolled 10-deep load batches (MLP=10);
//     g_part padded to 40 slices (37..39 never written -> exact zeros).
// ---------------------------------------------------------------------------

#define POP      4096
#define SPLITK   37
#define KCHUNK   112                 // 37*112 = 4144 (padded K; pad genomes -> 0)
#define LDT      136                 // padded smem tile row (halfs)
#define RSLICES  40                  // reduce reads 40 slices (4 groups x 10)

__device__ float g_part[RSLICES * 256 * 256];   // slices 37-39 stay zero

// ---------------- warp-MMA helpers (sm_80+ PTX, valid at compute_103 base) --
__device__ __forceinline__ unsigned smem_u32(const void* p) {
    unsigned a;
    asm("{ .reg .u64 t; cvta.to.shared.u64 t, %1; cvt.u32.u64 %0, t; }" : "=r"(a) : "l"(p));
    return a;
}
__device__ __forceinline__ void ldsm_x4_t(uint32_t* r, unsigned a) {
    asm volatile("ldmatrix.sync.aligned.m8n8.x4.trans.shared.b16 {%0,%1,%2,%3}, [%4];"
                 : "=r"(r[0]), "=r"(r[1]), "=r"(r[2]), "=r"(r[3]) : "r"(a));
}
__device__ __forceinline__ void ldsm_x2_t(uint32_t* r, unsigned a) {
    asm volatile("ldmatrix.sync.aligned.m8n8.x2.trans.shared.b16 {%0,%1}, [%2];"
                 : "=r"(r[0]), "=r"(r[1]) : "r"(a));
}
__device__ __forceinline__ void mma16816(float* d, const uint32_t* a, const uint32_t* b) {
    asm volatile("mma.sync.aligned.m16n8k16.row.col.f32.f16.f16.f32 "
                 "{%0,%1,%2,%3}, {%4,%5,%6,%7}, {%8,%9}, {%0,%1,%2,%3};"
                 : "+f"(d[0]), "+f"(d[1]), "+f"(d[2]), "+f"(d[3])
                 : "r"(a[0]), "r"(a[1]), "r"(a[2]), "r"(a[3]), "r"(b[0]), "r"(b[1]));
}

// ---------------------------------------------------------------------------
// Fused kernel: grid (2 mb, 2 nb, 37 z) = 148 CTAs (one full wave), 256 thr.
// Phase 1: generate As/Al (A hi/lo, k-major [112][LDT]) and Bs in smem.
// Phase 2: 128x128 fp32 accum via mma.sync, D += Ahi^T*B + Alo^T*B.
// ---------------------------------------------------------------------------
__global__ void __launch_bounds__(256, 1) fused_kernel(
        const float* __restrict__ w,
        const int*   __restrict__ idxg,
        const float* __restrict__ bbg) {
    extern __shared__ __half smem[];
    __half* As = smem;                       // [KCHUNK][LDT]
    __half* Al = smem + KCHUNK * LDT;
    __half* Bs = smem + 2 * KCHUNK * LDT;
    __shared__ float bb[144];
    __shared__ int   sidx[KCHUNK * 8];
    __shared__ float sw[KCHUNK];

    const int tid = threadIdx.x, lane = tid & 31, wid = tid >> 5;
    const int mb = blockIdx.x, nb = blockIdx.y, z = blockIdx.z;
    const int gbase = z * KCHUNK;

    // ---- Stage constants: building blocks, indices, weights (coalesced) ----
    if (tid < 144) bb[tid] = bbg[tid];
    #pragma unroll
    for (int i = tid; i < KCHUNK * 8; i += 256) {
        const int g = gbase + (i >> 3);
        sidx[i] = (g < POP) ? __ldg(&idxg[g * 8 + (i & 7)]) : 0;
    }
    if (tid < KCHUNK) {
        const int g = gbase + tid;
        sw[tid] = (g < POP) ? __ldg(&w[g]) : 0.f;   // w=0 -> zero A rows (pad)
    }
    __syncthreads();

    // ---- Phase 1a: A side (hi/lo). (g,x) tasks, x = mb*8 + xi ----
    for (int i = tid; i < KCHUNK * 8; i += 256) {
        const int gl = i >> 3, xi = i & 7;
        const int* ip = &sidx[gl * 8];
        const float u = bb[ip[0] * 4 + (mb & 1) * 2 + ((xi >> 1) & 1)]
                      * bb[ip[1] * 4 + ((xi >> 2) & 1) * 2 + (xi & 1)];
        float V[16];
        #pragma unroll
        for (int p = 0; p < 2; p++)
          #pragma unroll
          for (int q = 0; q < 2; q++)
            #pragma unroll
            for (int r = 0; r < 2; r++)
              #pragma unroll
              for (int s = 0; s < 2; s++)
                  V[(p*2+q)*4 + (r*2+s)] = bb[ip[2]*4 + p*2 + r] * bb[ip[3]*4 + q*2 + s];

        const float wf  = sw[gl];
        const float whf = __half2float(__float2half_rn(wf));
        const float wlf = __half2float(__float2half_rn(wf - whf));
        const __half2 ph = __float2half2_rn(whf * u);   // exact: {0, +/-w_hi}
        const __half2 pl = __float2half2_rn(wlf * u);

        const int colbase = (((xi >> 2) & 1) << 6) | ((xi & 3) << 2);
        #pragma unroll
        for (int qq = 0; qq < 4; qq++) {
            __half2 v0 = __floats2half2_rn(V[4*qq],   V[4*qq+1]);
            __half2 v1 = __floats2half2_rn(V[4*qq+2], V[4*qq+3]);
            __half2 h0 = __hmul2(ph, v0), h1 = __hmul2(ph, v1);
            __half2 l0 = __hmul2(pl, v0), l1 = __hmul2(pl, v1);
            const int col = colbase | (qq << 4);
            uint2 uh; uh.x = *(unsigned*)&h0; uh.y = *(unsigned*)&h1;
            uint2 ul; ul.x = *(unsigned*)&l0; ul.y = *(unsigned*)&l1;
            *(uint2*)&As[gl * LDT + col] = uh;
            *(uint2*)&Al[gl * LDT + col] = ul;
        }
    }

    // ---- Phase 1b: B side. (g,x) tasks, x = nb*8 + xi ----
    for (int i = tid; i < KCHUNK * 8; i += 256) {
        const int gl = i >> 3, xi = i & 7;
        const int* ip = &sidx[gl * 8];
        float u = bb[ip[4] * 4 + (nb & 1) * 2 + ((xi >> 1) & 1)]
                * bb[ip[5] * 4 + ((xi >> 2) & 1) * 2 + (xi & 1)];
        if (gbase + gl >= POP) u = 0.f;                // zero pad rows
        float V[16];
        #pragma unroll
        for (int p = 0; p < 2; p++)
          #pragma unroll
          for (int q = 0; q < 2; q++)
            #pragma unroll
            for (int r = 0; r < 2; r++)
              #pragma unroll
              for (int s = 0; s < 2; s++)
                  V[(p*2+q)*4 + (r*2+s)] = bb[ip[6]*4 + p*2 + r] * bb[ip[7]*4 + q*2 + s];

        const __half2 uh2 = __float2half2_rn(u);
        const int colbase = (((xi >> 2) & 1) << 6) | ((xi & 3) << 2);
        #pragma unroll
        for (int qq = 0; qq < 4; qq++) {
            __half2 v0 = __floats2half2_rn(V[4*qq],   V[4*qq+1]);
            __half2 v1 = __floats2half2_rn(V[4*qq+2], V[4*qq+3]);
            __half2 h0 = __hmul2(uh2, v0), h1 = __hmul2(uh2, v1);
            const int col = colbase | (qq << 4);
            uint2 uv; uv.x = *(unsigned*)&h0; uv.y = *(unsigned*)&h1;
            *(uint2*)&Bs[gl * LDT + col] = uv;
        }
    }
    __syncthreads();

    // ---- Phase 2: HMMA mainloop ----
    const int wm = wid & 1;                // m-half: 64 rows
    const int wn = wid >> 1;               // n-quarter: 32 cols
    const int arow = (lane & 7) + ((lane >> 4) << 3);
    const int acol = wm * 64 + ((lane >> 3) & 1) * 8;
    const int bl = lane & 15;
    const int brow = (bl & 7) + ((bl >> 3) << 3);

    const unsigned aHi = smem_u32(&As[arow * LDT + acol]);
    const unsigned aLo = smem_u32(&Al[arow * LDT + acol]);
    const unsigned bBa = smem_u32(&Bs[brow * LDT + wn * 32]);

    float acc[4][4][4];
    #pragma unroll
    for (int i = 0; i < 4; i++)
        #pragma unroll
        for (int j = 0; j < 4; j++)
            #pragma unroll
            for (int q = 0; q < 4; q++) acc[i][j][q] = 0.f;

    #pragma unroll
    for (int ks = 0; ks < KCHUNK / 16; ks++) {
        const unsigned ko = (unsigned)(ks * 16 * LDT * 2);
        uint32_t bf[4][2];
        #pragma unroll
        for (int nt = 0; nt < 4; nt++) ldsm_x2_t(bf[nt], bBa + ko + nt * 8 * 2);
        uint32_t ah[4][4], al[4][4];
        #pragma unroll
        for (int mt = 0; mt < 4; mt++) {
            ldsm_x4_t(ah[mt], aHi + ko + mt * 16 * 2);
            ldsm_x4_t(al[mt], aLo + ko + mt * 16 * 2);
        }
        #pragma unroll
        for (int mt = 0; mt < 4; mt++)
            #pragma unroll
            for (int nt = 0; nt < 4; nt++) {
                mma16816(acc[mt][nt], ah[mt], bf[nt]);
                mma16816(acc[mt][nt], al[mt], bf[nt]);
            }
    }

    // ---- Epilogue: write split-K partial ----
    float* part = g_part + z * 65536;
    const int r0 = mb * 128 + wm * 64;
    const int c0 = nb * 128 + wn * 32;
    #pragma unroll
    for (int mt = 0; mt < 4; mt++)
        #pragma unroll
        for (int nt = 0; nt < 4; nt++) {
            const int a = r0 + mt * 16 + (lane >> 2);
            const int b = c0 + nt * 8 + (lane & 3) * 2;
            *(float2*)&part[a * 256 + b]       = make_float2(acc[mt][nt][0], acc[mt][nt][1]);
            *(float2*)&part[(a + 8) * 256 + b] = make_float2(acc[mt][nt][2], acc[mt][nt][3]);
        }
}

// ---------------------------------------------------------------------------
// Reduce v3: 4 k-groups x 10 slices, CONSTANT loop bounds -> full unroll,
// 10 LDG.128 in flight per thread. grid 256 x 256 thr.
// ---------------------------------------------------------------------------
__global__ void __launch_bounds__(256) reduce_kernel(float* __restrict__ out) {
    __shared__ float4 red[3][64];
    const int t = threadIdx.x;
    const int t4 = blockIdx.x * 64 + (t & 63);
    const int ks = t >> 6;                           // 0..3
    const float4* src = (const float4*)g_part + (size_t)ks * 10 * 16384 + t4;

    float4 v[10];
    #pragma unroll
    for (int k = 0; k < 10; k++) v[k] = src[(size_t)k * 16384];   // batched LDGs

    float4 s = v[0];
    #pragma unroll
    for (int k = 1; k < 10; k++) {
        s.x += v[k].x; s.y += v[k].y; s.z += v[k].z; s.w += v[k].w;
    }
    if (ks > 0) red[ks - 1][t & 63] = s;
    __syncthreads();
    if (ks == 0) {
        #pragma unroll
        for (int j = 0; j < 3; j++) {
            float4 r = red[j][t];
            s.x += r.x; s.y += r.y; s.z += r.z; s.w += r.w;
        }
        const int tt = t4 * 4;
        const int a = tt >> 8, b = tt & 255;
        const int iH = a >> 4, jH = a & 15;
        const int iL = b >> 4, jL = b & 15;          // jL multiple of 4
        *(float4*)(out + (iH * 16 + iL) * 256 + jH * 16 + jL) = s;
    }
}

extern "C" void kernel_launch(void* const* d_in, const int* in_sizes, int n_in,
                              void* d_out, int out_size) {
    const float* w   = (const float*)d_in[0];
    const int*   idx = (const int*)  d_in[1];
    const float* bb  = (const float*)d_in[2];

    const int smem_bytes = 3 * KCHUNK * LDT * (int)sizeof(__half);  // 91392
    cudaFuncSetAttribute(fused_kernel, cudaFuncAttributeMaxDynamicSharedMemorySize, smem_bytes);

    fused_kernel<<<dim3(2, 2, SPLITK), 256, smem_bytes>>>(w, idx, bb);
    reduce_kernel<<<256, 256>>>((float*)d_out);
}